// round 15
// baseline (speedup 1.0000x reference)
#include <cuda_runtime.h>
#include <cuda_bf16.h>
#include <cuda_fp16.h>
#include <cstdint>

// Problem constants: x[8,2048,1024], W[1024,64]
#define BB 8
#define TT 2048
#define CC 1024
#define HH 64
#define NT 16            // T/128 tiles
#define NPAIR 136        // NT*(NT+1)/2 causal tile pairs

// Scratch (__device__ globals; no cudaMalloc allowed)
__device__ __nv_bfloat16 g_qh[BB * TT * HH];
__device__ __nv_bfloat16 g_ql[BB * TT * HH];
__device__ __nv_bfloat16 g_kh[BB * TT * HH];
__device__ __nv_bfloat16 g_kl[BB * TT * HH];
__device__ __half        g_vf[BB * TT * HH];      // V as single fp16
__device__ __half g_Sh[(size_t)BB * TT * TT];     // e' = exp(score - m_tile), fp16, [b][s][t]
__device__ float g_pm[(size_t)BB * TT * NT];      // per-tile row max, [b*TT+s][tile]
__device__ float g_pz[(size_t)BB * TT * NT];      // per-tile row sumexp
__device__ float g_sc[(size_t)BB * TT * NT];      // exp(pm - M) / Z
// W transposed+split to bf16 hi/lo, K-major: [which][n][k]
__device__ __nv_bfloat16 g_Wt_hi[3 * 64 * CC];
__device__ __nv_bfloat16 g_Wt_lo[3 * 64 * CC];

__device__ __forceinline__ void decode_pair(int p, int& ti, int& si)
{
    int t = (int)((sqrtf(8.f * p + 1.f) - 1.f) * 0.5f);
    while ((t + 1) * (t + 2) / 2 <= p) t++;
    while (t * (t + 1) / 2 > p) t--;
    ti = t;
    si = p - t * (t + 1) / 2;
}

__device__ __forceinline__ uint32_t smem_u32(const void* p)
{
    uint32_t a;
    asm("{ .reg .u64 t; cvta.to.shared.u64 t, %1; cvt.u32.u64 %0, t; }"
        : "=r"(a) : "l"(p));
    return a;
}

__device__ __forceinline__ void ldsm4(uint32_t* r, uint32_t addr)
{
    asm volatile("ldmatrix.sync.aligned.m8n8.x4.shared.b16 {%0,%1,%2,%3}, [%4];"
                 : "=r"(r[0]), "=r"(r[1]), "=r"(r[2]), "=r"(r[3]) : "r"(addr));
}

__device__ __forceinline__ void ldsm4t(uint32_t* r, uint32_t addr)
{
    asm volatile("ldmatrix.sync.aligned.m8n8.x4.trans.shared.b16 {%0,%1,%2,%3}, [%4];"
                 : "=r"(r[0]), "=r"(r[1]), "=r"(r[2]), "=r"(r[3]) : "r"(addr));
}

__device__ __forceinline__ void mma_bf16(float* c, const uint32_t* a,
                                         uint32_t b0, uint32_t b1)
{
    asm volatile("mma.sync.aligned.m16n8k16.row.col.f32.bf16.bf16.f32 "
                 "{%0,%1,%2,%3}, {%4,%5,%6,%7}, {%8,%9}, {%0,%1,%2,%3};"
                 : "+f"(c[0]), "+f"(c[1]), "+f"(c[2]), "+f"(c[3])
                 : "r"(a[0]), "r"(a[1]), "r"(a[2]), "r"(a[3]), "r"(b0), "r"(b1));
}

__device__ __forceinline__ void mma_f16(float* c, const uint32_t* a,
                                        uint32_t b0, uint32_t b1)
{
    asm volatile("mma.sync.aligned.m16n8k16.row.col.f32.f16.f16.f32 "
                 "{%0,%1,%2,%3}, {%4,%5,%6,%7}, {%8,%9}, {%0,%1,%2,%3};"
                 : "+f"(c[0]), "+f"(c[1]), "+f"(c[2]), "+f"(c[3])
                 : "r"(a[0]), "r"(a[1]), "r"(a[2]), "r"(a[3]), "r"(b0), "r"(b1));
}

// split 2 floats -> packed bf16 hi pair + lo pair
__device__ __forceinline__ void split_pack2(float a, float b, uint32_t& hh, uint32_t& ll)
{
    __nv_bfloat16 h0 = __float2bfloat16(a), h1 = __float2bfloat16(b);
    __nv_bfloat16 l0 = __float2bfloat16(a - __bfloat162float(h0));
    __nv_bfloat16 l1 = __float2bfloat16(b - __bfloat162float(h1));
    hh = (uint32_t)__bfloat16_as_ushort(h0) | ((uint32_t)__bfloat16_as_ushort(h1) << 16);
    ll = (uint32_t)__bfloat16_as_ushort(l0) | ((uint32_t)__bfloat16_as_ushort(l1) << 16);
}

// pack 2 floats -> fp16x2 (round to nearest)
__device__ __forceinline__ uint32_t pack2_h(float a, float b)
{
    __half2 h = __floats2half2_rn(a, b);
    return *(uint32_t*)&h;
}

// ---------------------------------------------------------------------------
// Kernel 0: transpose + bf16-split W -> g_Wt_hi/lo [which][n][k]
// ---------------------------------------------------------------------------
__global__ void convw_kernel(const float* __restrict__ Wq,
                             const float* __restrict__ Wk,
                             const float* __restrict__ Wv)
{
    const int w = blockIdx.y;
    const float* W = (w == 0) ? Wq : ((w == 1) ? Wk : Wv);
    int idx = blockIdx.x * 256 + threadIdx.x;   // 65536 per W
    int k = idx >> 6, n = idx & 63;
    float v = W[k * 64 + n];
    __nv_bfloat16 bh = __float2bfloat16(v);
    __nv_bfloat16 bl = __float2bfloat16(v - __bfloat162float(bh));
    g_Wt_hi[w * 64 * CC + n * CC + k] = bh;
    g_Wt_lo[w * 64 * CC + n * CC + k] = bl;
}

// ---------------------------------------------------------------------------
// Kernel 1: projections via mma.sync bf16-split (HMMA tensor path).
// CTA = 64 x-rows, 128 threads (4 warps x 16 rows), all 3 W (x read once).
// Small CTA -> 2-3 co-resident CTAs/SM so staging overlaps mma across CTAs.
// smem: Ah[64][72] 9216 | Al 9216 | Ws[3][2][64][72] 55296 = 73728 B.
// ---------------------------------------------------------------------------
#define AH_OFF 0
#define AL_OFF 9216
#define WS_OFF 18432
#define PJ_SMEM (18432 + 6 * 9216)   // 73728 B

__global__ __launch_bounds__(128) void proj_kernel(const float* __restrict__ x)
{
    extern __shared__ char smem[];
    const uint32_t sb = smem_u32(smem);
    const int tid = threadIdx.x;
    const int lane = tid & 31, wid = tid >> 5;   // wid 0..3
    const long r0 = (long)blockIdx.x * 64;

    float c[3][8][4];
#pragma unroll
    for (int w = 0; w < 3; w++)
#pragma unroll
        for (int nt = 0; nt < 8; nt++)
#pragma unroll
            for (int j = 0; j < 4; j++) c[w][nt][j] = 0.f;

    const int i8 = lane & 7, seg = lane >> 3;
    const uint32_t a_addr0 = sb + AH_OFF +
        (uint32_t)(wid * 16 + (seg & 1) * 8 + i8) * 144 + (seg >> 1) * 16;
    const uint32_t b_addr0 = sb + WS_OFF +
        (uint32_t)((seg >> 1) * 8 + i8) * 144 + (seg & 1) * 16;

    for (int kc = 0; kc < CC; kc += 64) {
        // stage x chunk: fp32 -> bf16 hi/lo, [row 0..63][k] padded rows
#pragma unroll
        for (int u = 0; u < 8; u++) {
            int idx = tid + u * 128;       // 0..1023
            int row = idx >> 4, k4 = idx & 15;
            float4 v = *(const float4*)&x[(r0 + row) * CC + kc + k4 * 4];
            uint32_t h0, l0, h1, l1;
            split_pack2(v.x, v.y, h0, l0);
            split_pack2(v.z, v.w, h1, l1);
            *(uint2*)(smem + AH_OFF + row * 144 + k4 * 8) = make_uint2(h0, h1);
            *(uint2*)(smem + AL_OFF + row * 144 + k4 * 8) = make_uint2(l0, l1);
        }
        // stage W chunk: [w][part][n][k]
#pragma unroll
        for (int u = 0; u < 24; u++) {
            int idx = tid + u * 128;       // 0..3071
            int wp = idx >> 9;             // 0..5 = w*2+part
            int rem = idx & 511;
            int n = rem >> 3, u16 = rem & 7;
            const __nv_bfloat16* src = (wp & 1) ? g_Wt_lo : g_Wt_hi;
            uint4 v = *(const uint4*)&src[((wp >> 1) * 64 + n) * CC + kc + u16 * 8];
            *(uint4*)(smem + WS_OFF + wp * 9216 + n * 144 + u16 * 16) = v;
        }
        __syncthreads();

#pragma unroll
        for (int ks = 0; ks < 4; ks++) {
            uint32_t ah[4], al[4];
            ldsm4(ah, a_addr0 + ks * 32);
            ldsm4(al, a_addr0 + (AL_OFF - AH_OFF) + ks * 32);
#pragma unroll
            for (int w = 0; w < 3; w++) {
#pragma unroll
                for (int p = 0; p < 4; p++) {
                    uint32_t bh[4], bl[4];
                    ldsm4(bh, b_addr0 + (w * 2) * 9216 + p * 2304 + ks * 32);
                    ldsm4(bl, b_addr0 + (w * 2 + 1) * 9216 + p * 2304 + ks * 32);
                    mma_bf16(c[w][2 * p],     ah, bh[0], bh[1]);
                    mma_bf16(c[w][2 * p],     ah, bl[0], bl[1]);
                    mma_bf16(c[w][2 * p],     al, bh[0], bh[1]);
                    mma_bf16(c[w][2 * p + 1], ah, bh[2], bh[3]);
                    mma_bf16(c[w][2 * p + 1], ah, bl[2], bl[3]);
                    mma_bf16(c[w][2 * p + 1], al, bh[2], bh[3]);
                }
            }
        }
        __syncthreads();
    }

    // epilogue: q/k -> pre-split bf16 hi/lo; v -> single fp16
    const long rowA = r0 + wid * 16 + (lane >> 2);
    const int col0 = (lane & 3) * 2;
#pragma unroll
    for (int w = 0; w < 2; w++) {
        __nv_bfloat16* dh = (w == 0) ? g_qh : g_kh;
        __nv_bfloat16* dl = (w == 0) ? g_ql : g_kl;
#pragma unroll
        for (int nt = 0; nt < 8; nt++) {
            uint32_t hh, ll;
            long off = rowA * HH + nt * 8 + col0;
            split_pack2(c[w][nt][0], c[w][nt][1], hh, ll);
            *(uint32_t*)(dh + off) = hh;
            *(uint32_t*)(dl + off) = ll;
            split_pack2(c[w][nt][2], c[w][nt][3], hh, ll);
            *(uint32_t*)(dh + off + 8 * HH) = hh;
            *(uint32_t*)(dl + off + 8 * HH) = ll;
        }
    }
#pragma unroll
    for (int nt = 0; nt < 8; nt++) {
        long off = rowA * HH + nt * 8 + col0;
        *(uint32_t*)(g_vf + off) = pack2_h(c[2][nt][0], c[2][nt][1]);
        *(uint32_t*)(g_vf + off + 8 * HH) = pack2_h(c[2][nt][2], c[2][nt][3]);
    }
}

// ---------------------------------------------------------------------------
// Kernel 2: S^T tile = K Q^T via HMMA bf16-split.
// Epilogue: per-s-row tile max m (register + 4 shfl), e' = exp(score - m),
// pairs written to a conflict-free smem tile (pitch 272B), then copied out
// to g_Sh with fully-coalesced 16B/thread stores. (pm, pz) -> g_pm/g_pz.
// ---------------------------------------------------------------------------
#define SG_AH 0
#define SG_AL 18432
#define SG_BH 36864
#define SG_BL 55296
#define SG_SMEM 73728

__global__ __launch_bounds__(256) void sgemm_kernel()
{
    extern __shared__ char smem[];
    const uint32_t sbm = smem_u32(smem);
    int ti, si;
    decode_pair(blockIdx.x, ti, si);
    const int b = blockIdx.y;
    const int s0 = si * 128, t0 = ti * 128;
    const int tid = threadIdx.x, lane = tid & 31, wid = tid >> 5;

    // stage K (A) and Q (B) hi/lo tiles
#pragma unroll
    for (int u = 0; u < 4; u++) {
        int unit = tid + u * 256;
        int row = unit >> 3, c8 = unit & 7;
        long koff = ((long)b * TT + s0 + row) * HH + c8 * 8;
        long qoff = ((long)b * TT + t0 + row) * HH + c8 * 8;
        *(uint4*)(smem + SG_AH + row * 144 + c8 * 16) = *(const uint4*)&g_kh[koff];
        *(uint4*)(smem + SG_AL + row * 144 + c8 * 16) = *(const uint4*)&g_kl[koff];
        *(uint4*)(smem + SG_BH + row * 144 + c8 * 16) = *(const uint4*)&g_qh[qoff];
        *(uint4*)(smem + SG_BL + row * 144 + c8 * 16) = *(const uint4*)&g_ql[qoff];
    }
    __syncthreads();

    const int i8 = lane & 7, seg = lane >> 3;
    const uint32_t aA = sbm + SG_AH +
        (uint32_t)(wid * 16 + (seg & 1) * 8 + i8) * 144 + (seg >> 1) * 16;
    const uint32_t aB = sbm + SG_BH +
        (uint32_t)((seg >> 1) * 8 + i8) * 144 + (seg & 1) * 16;

    float c[16][4];
#pragma unroll
    for (int n = 0; n < 16; n++)
#pragma unroll
        for (int j = 0; j < 4; j++) c[n][j] = 0.f;

#pragma unroll
    for (int ks = 0; ks < 4; ks++) {
        uint32_t ah[4], al[4];
        ldsm4(ah, aA + ks * 32);
        ldsm4(al, aA + (SG_AL - SG_AH) + ks * 32);
#pragma unroll
        for (int p = 0; p < 8; p++) {
            uint32_t bh[4], bl[4];
            ldsm4(bh, aB + p * 2304 + ks * 32);
            ldsm4(bl, aB + (SG_BL - SG_BH) + p * 2304 + ks * 32);
            mma_bf16(c[2 * p],     ah, bh[0], bh[1]);
            mma_bf16(c[2 * p],     ah, bl[0], bl[1]);
            mma_bf16(c[2 * p],     al, bh[0], bh[1]);
            mma_bf16(c[2 * p + 1], ah, bh[2], bh[3]);
            mma_bf16(c[2 * p + 1], ah, bl[2], bl[3]);
            mma_bf16(c[2 * p + 1], al, bh[2], bh[3]);
        }
    }
    __syncthreads();   // all smem reads done; reuse as e' staging tile

    // epilogue: per-s-row tile max, e' = exp(score - m), smem stage, z sums
    const int r_lo = wid * 16 + (lane >> 2);     // s-local row
    const int q2 = (lane & 3) * 2;               // t-local col base
    const int sA = s0 + r_lo, sB = sA + 8;

    float m0 = -1e30f, m1 = -1e30f;
#pragma unroll
    for (int n = 0; n < 16; n++) {
        const int tc = t0 + n * 8 + q2;
        if (tc     >= sA) m0 = fmaxf(m0, c[n][0]);
        if (tc + 1 >= sA) m0 = fmaxf(m0, c[n][1]);
        if (tc     >= sB) m1 = fmaxf(m1, c[n][2]);
        if (tc + 1 >= sB) m1 = fmaxf(m1, c[n][3]);
    }
    m0 = fmaxf(m0, __shfl_xor_sync(0xffffffffu, m0, 1));
    m0 = fmaxf(m0, __shfl_xor_sync(0xffffffffu, m0, 2));
    m1 = fmaxf(m1, __shfl_xor_sync(0xffffffffu, m1, 1));
    m1 = fmaxf(m1, __shfl_xor_sync(0xffffffffu, m1, 2));

    float z0 = 0.f, z1 = 0.f;
#pragma unroll
    for (int n = 0; n < 16; n++) {
        const int tc = t0 + n * 8 + q2;
        const int tl = n * 8 + q2;               // t-local
        float e00 = (tc     >= sA) ? __expf(c[n][0] - m0) : 0.f;
        float e01 = (tc + 1 >= sA) ? __expf(c[n][1] - m0) : 0.f;
        float e10 = (tc     >= sB) ? __expf(c[n][2] - m1) : 0.f;
        float e11 = (tc + 1 >= sB) ? __expf(c[n][3] - m1) : 0.f;
        *(uint32_t*)(smem + r_lo * 272 + tl * 2)       = pack2_h(e00, e01);
        *(uint32_t*)(smem + (r_lo + 8) * 272 + tl * 2) = pack2_h(e10, e11);
        z0 += e00 + e01;
        z1 += e10 + e11;
    }
    z0 += __shfl_xor_sync(0xffffffffu, z0, 1);
    z0 += __shfl_xor_sync(0xffffffffu, z0, 2);
    z1 += __shfl_xor_sync(0xffffffffu, z1, 1);
    z1 += __shfl_xor_sync(0xffffffffu, z1, 2);
    if ((lane & 3) == 0) {
        g_pm[((size_t)b * TT + sA) * NT + ti] = m0;
        g_pz[((size_t)b * TT + sA) * NT + ti] = z0;
        g_pm[((size_t)b * TT + sB) * NT + ti] = m1;
        g_pz[((size_t)b * TT + sB) * NT + ti] = z1;
    }
    __syncthreads();

    // coalesced copy-out: 16 threads per row, 16B per thread = 256B segments
#pragma unroll
    for (int j = 0; j < 8; j++) {
        int idx = tid + j * 256;           // 0..2047
        int row = idx >> 4, c16 = idx & 15;
        *(uint4*)&g_Sh[((size_t)b * TT + s0 + row) * TT + t0 + c16 * 8] =
            *(uint4*)(smem + row * 272 + c16 * 16);
    }
}

// ---------------------------------------------------------------------------
// Kernel 3: merge tile partials -> per-(s, tile) scale = exp(pm - M)/Z.
// Vectorized float4 loads/stores; c<st entries are zero-init (device globals)
// and masked in registers before use.
// ---------------------------------------------------------------------------
__global__ void merge_kernel()
{
    int i = blockIdx.x * blockDim.x + threadIdx.x;
    if (i >= BB * TT) return;
    const int s = i % TT;
    const int st = s >> 7;

    float pm[NT], pz[NT];
#pragma unroll
    for (int v = 0; v < 4; v++) {
        *(float4*)&pm[v * 4] = *(const float4*)&g_pm[(size_t)i * NT + v * 4];
        *(float4*)&pz[v * 4] = *(const float4*)&g_pz[(size_t)i * NT + v * 4];
    }
    float m = -1e30f;
#pragma unroll
    for (int c = 0; c < NT; c++)
        m = fmaxf(m, (c >= st) ? pm[c] : -1e30f);
    float z = 0.f;
#pragma unroll
    for (int c = 0; c < NT; c++)
        z += (c >= st) ? pz[c] * __expf(pm[c] - m) : 0.f;
    float zi = 1.f / z;
    float sc[NT];
#pragma unroll
    for (int c = 0; c < NT; c++)
        sc[c] = (c >= st) ? __expf(pm[c] - m) * zi : 0.f;
#pragma unroll
    for (int v = 0; v < 4; v++)
        *(float4*)&g_sc[(size_t)i * NT + v * 4] = *(float4*)&sc[v * 4];
}

// ---------------------------------------------------------------------------
// Kernel 4: O += e' V' via fp16 HMMA, where V' = sc[s,ti] * V (scale folded
// into the V operand). e' tile staged as a RAW fp16 copy. atomicAdd into out.
// smem: Pt [128 s][136 t]h pitch 272B (34816), Vf [128][72]h pitch 144B.
// ---------------------------------------------------------------------------
#define PV_PH 0
#define PV_VF 34816
#define PV_SMEM 53248

__global__ __launch_bounds__(256) void pv_kernel(float* __restrict__ out)
{
    const int ti = blockIdx.x, cc = blockIdx.y, b = blockIdx.z;
    if (2 * cc > ti) return;

    extern __shared__ char smem[];
    const uint32_t sbm = smem_u32(smem);
    const int tid = threadIdx.x, lane = tid & 31, wid = tid >> 5;
    const int t0 = ti * 128;

    const int i8 = lane & 7;
    // A (P, rows t) from transposed ldsm on Pt[s][t]
    const uint32_t aP = sbm + PV_PH +
        (uint32_t)((lane >> 4) * 8 + i8) * 272 +
        (uint32_t)(wid * 16 + ((lane >> 3) & 1) * 8) * 2;
    const uint32_t aV = sbm + PV_VF + (uint32_t)(lane & 15) * 144 + (lane >> 4) * 16;

    float c[8][4];
#pragma unroll
    for (int n = 0; n < 8; n++)
#pragma unroll
        for (int j = 0; j < 4; j++) c[n][j] = 0.f;

    for (int st = 2 * cc; st <= ti && st <= 2 * cc + 1; st++) {
        const int s0 = st * 128;
        __syncthreads();

        // stage e' tile: raw fp16 copy, 32KB (no arithmetic)
#pragma unroll
        for (int j = 0; j < 8; j++) {
            int idx = tid + j * 256;           // 0..2047
            int row = idx >> 4, c16 = idx & 15;
            *(uint4*)(smem + PV_PH + row * 272 + c16 * 16) =
                *(const uint4*)&g_Sh[((size_t)b * TT + s0 + row) * TT + t0 + c16 * 8];
        }

        // stage V' = sc * V (fp16), scale uniform per s-row
#pragma unroll
        for (int u = 0; u < 4; u++) {
            int unit = tid + u * 256;
            int row = unit >> 3, c8 = unit & 7;
            float sc = g_sc[((size_t)b * TT + s0 + row) * NT + ti];
            __half2 sch = __float2half2_rn(sc);
            uint4 v = *(const uint4*)&g_vf[((long)b * TT + s0 + row) * HH + c8 * 8];
            __half2* vh = (__half2*)&v;
            vh[0] = __hmul2(vh[0], sch);
            vh[1] = __hmul2(vh[1], sch);
            vh[2] = __hmul2(vh[2], sch);
            vh[3] = __hmul2(vh[3], sch);
            *(uint4*)(smem + PV_VF + row * 144 + c8 * 16) = v;
        }
        __syncthreads();

#pragma unroll
        for (int ks = 0; ks < 8; ks++) {
            uint32_t ah[4];
            ldsm4t(ah, aP + ks * 4352);          // 16 s-rows * 272B
#pragma unroll
            for (int g = 0; g < 4; g++) {
                uint32_t bv[4];
                ldsm4t(bv, aV + ks * 2304 + g * 32);
                mma_f16(c[2 * g],     ah, bv[0], bv[1]);
                mma_f16(c[2 * g + 1], ah, bv[2], bv[3]);
            }
        }
    }

    const long rowA = (long)b * TT + t0 + wid * 16 + (lane >> 2);
    const int col0 = (lane & 3) * 2;
#pragma unroll
    for (int n = 0; n < 8; n++) {
        float* o = &out[rowA * HH + n * 8 + col0];
        atomicAdd(&o[0], c[n][0]);
        atomicAdd(&o[1], c[n][1]);
        atomicAdd(&o[8 * HH + 0], c[n][2]);
        atomicAdd(&o[8 * HH + 1], c[n][3]);
    }
}

// ---------------------------------------------------------------------------
extern "C" void kernel_launch(void* const* d_in, const int* in_sizes, int n_in,
                              void* d_out, int out_size)
{
    const float* x  = (const float*)d_in[0];
    const float* Wq = (const float*)d_in[1];
    const float* Wk = (const float*)d_in[2];
    const float* Wv = (const float*)d_in[3];
    float* out = (float*)d_out;

    cudaFuncSetAttribute(proj_kernel, cudaFuncAttributeMaxDynamicSharedMemorySize,
                         PJ_SMEM);
    cudaFuncSetAttribute(sgemm_kernel, cudaFuncAttributeMaxDynamicSharedMemorySize,
                         SG_SMEM);
    cudaFuncSetAttribute(pv_kernel, cudaFuncAttributeMaxDynamicSharedMemorySize,
                         PV_SMEM);

    cudaMemsetAsync(out, 0, (size_t)out_size * sizeof(float), 0);

    convw_kernel<<<dim3(256, 3, 1), 256>>>(Wq, Wk, Wv);
    proj_kernel<<<BB * TT / 64, 128, PJ_SMEM>>>(x);
    sgemm_kernel<<<dim3(NPAIR, BB, 1), 256, SG_SMEM>>>();
    merge_kernel<<<128, 128>>>();
    pv_kernel<<<dim3(NT, 8, BB), 256, PV_SMEM>>>(out);
}

// round 16
// speedup vs baseline: 1.1855x; 1.1855x over previous
#include <cuda_runtime.h>
#include <cuda_bf16.h>
#include <cuda_fp16.h>
#include <cstdint>

// Problem constants: x[8,2048,1024], W[1024,64]
#define BB 8
#define TT 2048
#define CC 1024
#define HH 64
#define NT 16            // T/128 tiles
#define NPAIR 136        // NT*(NT+1)/2 causal tile pairs

// Scratch (__device__ globals; no cudaMalloc allowed)
__device__ __nv_bfloat16 g_qh[BB * TT * HH];
__device__ __nv_bfloat16 g_ql[BB * TT * HH];
__device__ __nv_bfloat16 g_kh[BB * TT * HH];
__device__ __nv_bfloat16 g_kl[BB * TT * HH];
__device__ __half        g_vf[BB * TT * HH];      // V as single fp16
__device__ __half g_Sh[(size_t)BB * TT * TT];     // e' = exp(score - m_tile), fp16, [b][s][t]
__device__ float g_pm[(size_t)BB * TT * NT];      // per-tile row max, [b*TT+s][tile]
__device__ float g_pz[(size_t)BB * TT * NT];      // per-tile row sumexp
__device__ float g_sc[(size_t)BB * TT * NT];      // exp(pm - M) / Z
// W transposed+split to bf16 hi/lo, K-major: [which][n][k]
__device__ __nv_bfloat16 g_Wt_hi[3 * 64 * CC];
__device__ __nv_bfloat16 g_Wt_lo[3 * 64 * CC];

__device__ __forceinline__ void decode_pair(int p, int& ti, int& si)
{
    int t = (int)((sqrtf(8.f * p + 1.f) - 1.f) * 0.5f);
    while ((t + 1) * (t + 2) / 2 <= p) t++;
    while (t * (t + 1) / 2 > p) t--;
    ti = t;
    si = p - t * (t + 1) / 2;
}

__device__ __forceinline__ uint32_t smem_u32(const void* p)
{
    uint32_t a;
    asm("{ .reg .u64 t; cvta.to.shared.u64 t, %1; cvt.u32.u64 %0, t; }"
        : "=r"(a) : "l"(p));
    return a;
}

__device__ __forceinline__ void ldsm4(uint32_t* r, uint32_t addr)
{
    asm volatile("ldmatrix.sync.aligned.m8n8.x4.shared.b16 {%0,%1,%2,%3}, [%4];"
                 : "=r"(r[0]), "=r"(r[1]), "=r"(r[2]), "=r"(r[3]) : "r"(addr));
}

__device__ __forceinline__ void ldsm4t(uint32_t* r, uint32_t addr)
{
    asm volatile("ldmatrix.sync.aligned.m8n8.x4.trans.shared.b16 {%0,%1,%2,%3}, [%4];"
                 : "=r"(r[0]), "=r"(r[1]), "=r"(r[2]), "=r"(r[3]) : "r"(addr));
}

__device__ __forceinline__ void mma_bf16(float* c, const uint32_t* a,
                                         uint32_t b0, uint32_t b1)
{
    asm volatile("mma.sync.aligned.m16n8k16.row.col.f32.bf16.bf16.f32 "
                 "{%0,%1,%2,%3}, {%4,%5,%6,%7}, {%8,%9}, {%0,%1,%2,%3};"
                 : "+f"(c[0]), "+f"(c[1]), "+f"(c[2]), "+f"(c[3])
                 : "r"(a[0]), "r"(a[1]), "r"(a[2]), "r"(a[3]), "r"(b0), "r"(b1));
}

__device__ __forceinline__ void mma_f16(float* c, const uint32_t* a,
                                        uint32_t b0, uint32_t b1)
{
    asm volatile("mma.sync.aligned.m16n8k16.row.col.f32.f16.f16.f32 "
                 "{%0,%1,%2,%3}, {%4,%5,%6,%7}, {%8,%9}, {%0,%1,%2,%3};"
                 : "+f"(c[0]), "+f"(c[1]), "+f"(c[2]), "+f"(c[3])
                 : "r"(a[0]), "r"(a[1]), "r"(a[2]), "r"(a[3]), "r"(b0), "r"(b1));
}

// split 2 floats -> packed bf16 hi pair + lo pair
__device__ __forceinline__ void split_pack2(float a, float b, uint32_t& hh, uint32_t& ll)
{
    __nv_bfloat16 h0 = __float2bfloat16(a), h1 = __float2bfloat16(b);
    __nv_bfloat16 l0 = __float2bfloat16(a - __bfloat162float(h0));
    __nv_bfloat16 l1 = __float2bfloat16(b - __bfloat162float(h1));
    hh = (uint32_t)__bfloat16_as_ushort(h0) | ((uint32_t)__bfloat16_as_ushort(h1) << 16);
    ll = (uint32_t)__bfloat16_as_ushort(l0) | ((uint32_t)__bfloat16_as_ushort(l1) << 16);
}

// pack 2 floats -> fp16x2 (round to nearest)
__device__ __forceinline__ uint32_t pack2_h(float a, float b)
{
    __half2 h = __floats2half2_rn(a, b);
    return *(uint32_t*)&h;
}

// ---------------------------------------------------------------------------
// Kernel 0: transpose + bf16-split W -> g_Wt_hi/lo [which][n][k]
// ---------------------------------------------------------------------------
__global__ void convw_kernel(const float* __restrict__ Wq,
                             const float* __restrict__ Wk,
                             const float* __restrict__ Wv)
{
    const int w = blockIdx.y;
    const float* W = (w == 0) ? Wq : ((w == 1) ? Wk : Wv);
    int idx = blockIdx.x * 256 + threadIdx.x;   // 65536 per W
    int k = idx >> 6, n = idx & 63;
    float v = W[k * 64 + n];
    __nv_bfloat16 bh = __float2bfloat16(v);
    __nv_bfloat16 bl = __float2bfloat16(v - __bfloat162float(bh));
    g_Wt_hi[w * 64 * CC + n * CC + k] = bh;
    g_Wt_lo[w * 64 * CC + n * CC + k] = bl;
}

// ---------------------------------------------------------------------------
// Kernel 1: projections via mma.sync bf16-split (HMMA tensor path).
// CTA = 128 x-rows, 8 warps x 16 rows, all 3 W (x read once).  (round-14)
// ---------------------------------------------------------------------------
#define AH_OFF 0
#define AL_OFF 18432
#define WS_OFF 36864
#define PJ_SMEM (36864 + 6 * 9216)   // 92160 B

__global__ __launch_bounds__(256, 1) void proj_kernel(const float* __restrict__ x)
{
    extern __shared__ char smem[];
    const uint32_t sb = smem_u32(smem);
    const int tid = threadIdx.x;
    const int lane = tid & 31, wid = tid >> 5;
    const long r0 = (long)blockIdx.x * 128;

    float c[3][8][4];
#pragma unroll
    for (int w = 0; w < 3; w++)
#pragma unroll
        for (int nt = 0; nt < 8; nt++)
#pragma unroll
            for (int j = 0; j < 4; j++) c[w][nt][j] = 0.f;

    const int i8 = lane & 7, seg = lane >> 3;
    const uint32_t a_addr0 = sb + AH_OFF +
        (uint32_t)(wid * 16 + (seg & 1) * 8 + i8) * 144 + (seg >> 1) * 16;
    const uint32_t b_addr0 = sb + WS_OFF +
        (uint32_t)((seg >> 1) * 8 + i8) * 144 + (seg & 1) * 16;

    for (int kc = 0; kc < CC; kc += 64) {
        // stage x chunk: fp32 -> bf16 hi/lo, [row][k] padded rows
#pragma unroll
        for (int u = 0; u < 8; u++) {
            int idx = tid + u * 256;       // 0..2047
            int row = idx >> 4, k4 = idx & 15;
            float4 v = *(const float4*)&x[(r0 + row) * CC + kc + k4 * 4];
            uint32_t h0, l0, h1, l1;
            split_pack2(v.x, v.y, h0, l0);
            split_pack2(v.z, v.w, h1, l1);
            *(uint2*)(smem + AH_OFF + row * 144 + k4 * 8) = make_uint2(h0, h1);
            *(uint2*)(smem + AL_OFF + row * 144 + k4 * 8) = make_uint2(l0, l1);
        }
        // stage W chunk: [w][part][n][k]
#pragma unroll
        for (int u = 0; u < 12; u++) {
            int idx = tid + u * 256;       // 0..3071
            int wp = idx >> 9;             // 0..5 = w*2+part
            int rem = idx & 511;
            int n = rem >> 3, u16 = rem & 7;
            const __nv_bfloat16* src = (wp & 1) ? g_Wt_lo : g_Wt_hi;
            uint4 v = *(const uint4*)&src[((wp >> 1) * 64 + n) * CC + kc + u16 * 8];
            *(uint4*)(smem + WS_OFF + wp * 9216 + n * 144 + u16 * 16) = v;
        }
        __syncthreads();

#pragma unroll
        for (int ks = 0; ks < 4; ks++) {
            uint32_t ah[4], al[4];
            ldsm4(ah, a_addr0 + ks * 32);
            ldsm4(al, a_addr0 + (AL_OFF - AH_OFF) + ks * 32);
#pragma unroll
            for (int w = 0; w < 3; w++) {
#pragma unroll
                for (int p = 0; p < 4; p++) {
                    uint32_t bh[4], bl[4];
                    ldsm4(bh, b_addr0 + (w * 2) * 9216 + p * 2304 + ks * 32);
                    ldsm4(bl, b_addr0 + (w * 2 + 1) * 9216 + p * 2304 + ks * 32);
                    mma_bf16(c[w][2 * p],     ah, bh[0], bh[1]);
                    mma_bf16(c[w][2 * p],     ah, bl[0], bl[1]);
                    mma_bf16(c[w][2 * p],     al, bh[0], bh[1]);
                    mma_bf16(c[w][2 * p + 1], ah, bh[2], bh[3]);
                    mma_bf16(c[w][2 * p + 1], ah, bl[2], bl[3]);
                    mma_bf16(c[w][2 * p + 1], al, bh[2], bh[3]);
                }
            }
        }
        __syncthreads();
    }

    // epilogue: q/k -> pre-split bf16 hi/lo; v -> single fp16
    const long rowA = r0 + wid * 16 + (lane >> 2);
    const int col0 = (lane & 3) * 2;
#pragma unroll
    for (int w = 0; w < 2; w++) {
        __nv_bfloat16* dh = (w == 0) ? g_qh : g_kh;
        __nv_bfloat16* dl = (w == 0) ? g_ql : g_kl;
#pragma unroll
        for (int nt = 0; nt < 8; nt++) {
            uint32_t hh, ll;
            long off = rowA * HH + nt * 8 + col0;
            split_pack2(c[w][nt][0], c[w][nt][1], hh, ll);
            *(uint32_t*)(dh + off) = hh;
            *(uint32_t*)(dl + off) = ll;
            split_pack2(c[w][nt][2], c[w][nt][3], hh, ll);
            *(uint32_t*)(dh + off + 8 * HH) = hh;
            *(uint32_t*)(dl + off + 8 * HH) = ll;
        }
    }
#pragma unroll
    for (int nt = 0; nt < 8; nt++) {
        long off = rowA * HH + nt * 8 + col0;
        *(uint32_t*)(g_vf + off) = pack2_h(c[2][nt][0], c[2][nt][1]);
        *(uint32_t*)(g_vf + off + 8 * HH) = pack2_h(c[2][nt][2], c[2][nt][3]);
    }
}

// ---------------------------------------------------------------------------
// Kernel 2: S^T tile = K Q^T via HMMA bf16-split.
// Epilogue: per-s-row tile max m (register + 4 shfl), e' = exp(score - m),
// pairs staged to conflict-free smem, coalesced 16B copy-out. (round-14)
// ---------------------------------------------------------------------------
#define SG_AH 0
#define SG_AL 18432
#define SG_BH 36864
#define SG_BL 55296
#define SG_SMEM 73728

__global__ __launch_bounds__(256) void sgemm_kernel()
{
    extern __shared__ char smem[];
    const uint32_t sbm = smem_u32(smem);
    int ti, si;
    decode_pair(blockIdx.x, ti, si);
    const int b = blockIdx.y;
    const int s0 = si * 128, t0 = ti * 128;
    const int tid = threadIdx.x, lane = tid & 31, wid = tid >> 5;

    // stage K (A) and Q (B) hi/lo tiles
#pragma unroll
    for (int u = 0; u < 4; u++) {
        int unit = tid + u * 256;
        int row = unit >> 3, c8 = unit & 7;
        long koff = ((long)b * TT + s0 + row) * HH + c8 * 8;
        long qoff = ((long)b * TT + t0 + row) * HH + c8 * 8;
        *(uint4*)(smem + SG_AH + row * 144 + c8 * 16) = *(const uint4*)&g_kh[koff];
        *(uint4*)(smem + SG_AL + row * 144 + c8 * 16) = *(const uint4*)&g_kl[koff];
        *(uint4*)(smem + SG_BH + row * 144 + c8 * 16) = *(const uint4*)&g_qh[qoff];
        *(uint4*)(smem + SG_BL + row * 144 + c8 * 16) = *(const uint4*)&g_ql[qoff];
    }
    __syncthreads();

    const int i8 = lane & 7, seg = lane >> 3;
    const uint32_t aA = sbm + SG_AH +
        (uint32_t)(wid * 16 + (seg & 1) * 8 + i8) * 144 + (seg >> 1) * 16;
    const uint32_t aB = sbm + SG_BH +
        (uint32_t)((seg >> 1) * 8 + i8) * 144 + (seg & 1) * 16;

    float c[16][4];
#pragma unroll
    for (int n = 0; n < 16; n++)
#pragma unroll
        for (int j = 0; j < 4; j++) c[n][j] = 0.f;

#pragma unroll
    for (int ks = 0; ks < 4; ks++) {
        uint32_t ah[4], al[4];
        ldsm4(ah, aA + ks * 32);
        ldsm4(al, aA + (SG_AL - SG_AH) + ks * 32);
#pragma unroll
        for (int p = 0; p < 8; p++) {
            uint32_t bh[4], bl[4];
            ldsm4(bh, aB + p * 2304 + ks * 32);
            ldsm4(bl, aB + (SG_BL - SG_BH) + p * 2304 + ks * 32);
            mma_bf16(c[2 * p],     ah, bh[0], bh[1]);
            mma_bf16(c[2 * p],     ah, bl[0], bl[1]);
            mma_bf16(c[2 * p],     al, bh[0], bh[1]);
            mma_bf16(c[2 * p + 1], ah, bh[2], bh[3]);
            mma_bf16(c[2 * p + 1], ah, bl[2], bl[3]);
            mma_bf16(c[2 * p + 1], al, bh[2], bh[3]);
        }
    }
    __syncthreads();   // all smem reads done; reuse as e' staging tile

    // epilogue: per-s-row tile max, e' = exp(score - m), smem stage, z sums
    const int r_lo = wid * 16 + (lane >> 2);     // s-local row
    const int q2 = (lane & 3) * 2;               // t-local col base
    const int sA = s0 + r_lo, sB = sA + 8;

    float m0 = -1e30f, m1 = -1e30f;
#pragma unroll
    for (int n = 0; n < 16; n++) {
        const int tc = t0 + n * 8 + q2;
        if (tc     >= sA) m0 = fmaxf(m0, c[n][0]);
        if (tc + 1 >= sA) m0 = fmaxf(m0, c[n][1]);
        if (tc     >= sB) m1 = fmaxf(m1, c[n][2]);
        if (tc + 1 >= sB) m1 = fmaxf(m1, c[n][3]);
    }
    m0 = fmaxf(m0, __shfl_xor_sync(0xffffffffu, m0, 1));
    m0 = fmaxf(m0, __shfl_xor_sync(0xffffffffu, m0, 2));
    m1 = fmaxf(m1, __shfl_xor_sync(0xffffffffu, m1, 1));
    m1 = fmaxf(m1, __shfl_xor_sync(0xffffffffu, m1, 2));

    float z0 = 0.f, z1 = 0.f;
#pragma unroll
    for (int n = 0; n < 16; n++) {
        const int tc = t0 + n * 8 + q2;
        const int tl = n * 8 + q2;               // t-local
        float e00 = (tc     >= sA) ? __expf(c[n][0] - m0) : 0.f;
        float e01 = (tc + 1 >= sA) ? __expf(c[n][1] - m0) : 0.f;
        float e10 = (tc     >= sB) ? __expf(c[n][2] - m1) : 0.f;
        float e11 = (tc + 1 >= sB) ? __expf(c[n][3] - m1) : 0.f;
        *(uint32_t*)(smem + r_lo * 272 + tl * 2)       = pack2_h(e00, e01);
        *(uint32_t*)(smem + (r_lo + 8) * 272 + tl * 2) = pack2_h(e10, e11);
        z0 += e00 + e01;
        z1 += e10 + e11;
    }
    z0 += __shfl_xor_sync(0xffffffffu, z0, 1);
    z0 += __shfl_xor_sync(0xffffffffu, z0, 2);
    z1 += __shfl_xor_sync(0xffffffffu, z1, 1);
    z1 += __shfl_xor_sync(0xffffffffu, z1, 2);
    if ((lane & 3) == 0) {
        g_pm[((size_t)b * TT + sA) * NT + ti] = m0;
        g_pz[((size_t)b * TT + sA) * NT + ti] = z0;
        g_pm[((size_t)b * TT + sB) * NT + ti] = m1;
        g_pz[((size_t)b * TT + sB) * NT + ti] = z1;
    }
    __syncthreads();

    // coalesced copy-out: 16 threads per row, 16B per thread = 256B segments
#pragma unroll
    for (int j = 0; j < 8; j++) {
        int idx = tid + j * 256;           // 0..2047
        int row = idx >> 4, c16 = idx & 15;
        *(uint4*)&g_Sh[((size_t)b * TT + s0 + row) * TT + t0 + c16 * 8] =
            *(uint4*)(smem + row * 272 + c16 * 16);
    }
}

// ---------------------------------------------------------------------------
// Kernel 3: merge tile partials -> per-(s, tile) scale = exp(pm - M)/Z.
// 4 threads per column: each owns 4 contiguous tile-entries (float4 load),
// width-4 butterfly combine for (max, z), each lane writes its own float4.
// 64K threads -> 4x MLP vs the 1-thread-per-column version.
// ---------------------------------------------------------------------------
__global__ void merge_kernel()
{
    int gtid = blockIdx.x * blockDim.x + threadIdx.x;
    int i = gtid >> 2;                 // column index (b*TT+s)
    int q = gtid & 3;                  // which 4-entry group
    if (i >= BB * TT) return;
    const int s = i % TT;
    const int st = s >> 7;

    float pm[4], pz[4];
    *(float4*)pm = *(const float4*)&g_pm[(size_t)i * NT + q * 4];
    *(float4*)pz = *(const float4*)&g_pz[(size_t)i * NT + q * 4];

    float m = -1e30f;
#pragma unroll
    for (int j = 0; j < 4; j++)
        m = fmaxf(m, (q * 4 + j >= st) ? pm[j] : -1e30f);
    m = fmaxf(m, __shfl_xor_sync(0xffffffffu, m, 1, 4));
    m = fmaxf(m, __shfl_xor_sync(0xffffffffu, m, 2, 4));

    float z = 0.f;
#pragma unroll
    for (int j = 0; j < 4; j++)
        z += (q * 4 + j >= st) ? pz[j] * __expf(pm[j] - m) : 0.f;
    z += __shfl_xor_sync(0xffffffffu, z, 1, 4);
    z += __shfl_xor_sync(0xffffffffu, z, 2, 4);

    float zi = 1.f / z;
    float sc[4];
#pragma unroll
    for (int j = 0; j < 4; j++)
        sc[j] = (q * 4 + j >= st) ? __expf(pm[j] - m) * zi : 0.f;
    *(float4*)&g_sc[(size_t)i * NT + q * 4] = *(float4*)sc;
}

// ---------------------------------------------------------------------------
// Kernel 4: O += e' V' via fp16 HMMA, where V' = sc[s,ti] * V (scale folded
// into the V operand). e' tile staged as a RAW fp16 copy. atomicAdd into out.
// Grid: packed (ti, cc) pairs in x (72 per batch), batch in y — no dead blocks.
// smem: Pt [128 s][136 t]h pitch 272B (34816), Vf [128][72]h pitch 144B.
// ---------------------------------------------------------------------------
#define PV_PH 0
#define PV_VF 34816
#define PV_SMEM 53248
#define PV_NPAIR 72     // sum over ti of (ti/2 + 1)

__global__ __launch_bounds__(256) void pv_kernel(float* __restrict__ out)
{
    // decode packed (ti, cc): pair p -> ti with offset; ti has ti/2+1 cc slots
    int p = blockIdx.x;
    int ti = 0;
    {
        // cumulative slots: C(t) = sum_{u<=t}(u/2+1); find ti s.t. p in range
        int acc = 0;
#pragma unroll
        for (int t = 0; t < NT; t++) {
            int w = t / 2 + 1;
            if (p < acc + w) { ti = t; break; }
            acc += w;
        }
        int base = 0;
        for (int t = 0; t < ti; t++) base += t / 2 + 1;
        p -= base;                      // p = cc in 0..ti/2
    }
    const int cc = p, b = blockIdx.y;

    extern __shared__ char smem[];
    const uint32_t sbm = smem_u32(smem);
    const int tid = threadIdx.x, lane = tid & 31, wid = tid >> 5;
    const int t0 = ti * 128;

    const int i8 = lane & 7;
    const uint32_t aP = sbm + PV_PH +
        (uint32_t)((lane >> 4) * 8 + i8) * 272 +
        (uint32_t)(wid * 16 + ((lane >> 3) & 1) * 8) * 2;
    const uint32_t aV = sbm + PV_VF + (uint32_t)(lane & 15) * 144 + (lane >> 4) * 16;

    float c[8][4];
#pragma unroll
    for (int n = 0; n < 8; n++)
#pragma unroll
        for (int j = 0; j < 4; j++) c[n][j] = 0.f;

    for (int st = 2 * cc; st <= ti && st <= 2 * cc + 1; st++) {
        const int s0 = st * 128;
        __syncthreads();

        // stage e' tile: raw fp16 copy, 32KB (no arithmetic)
#pragma unroll
        for (int j = 0; j < 8; j++) {
            int idx = tid + j * 256;           // 0..2047
            int row = idx >> 4, c16 = idx & 15;
            *(uint4*)(smem + PV_PH + row * 272 + c16 * 16) =
                *(const uint4*)&g_Sh[((size_t)b * TT + s0 + row) * TT + t0 + c16 * 8];
        }

        // stage V' = sc * V (fp16), scale uniform per s-row
#pragma unroll
        for (int u = 0; u < 4; u++) {
            int unit = tid + u * 256;
            int row = unit >> 3, c8 = unit & 7;
            float sc = g_sc[((size_t)b * TT + s0 + row) * NT + ti];
            __half2 sch = __float2half2_rn(sc);
            uint4 v = *(const uint4*)&g_vf[((long)b * TT + s0 + row) * HH + c8 * 8];
            __half2* vh = (__half2*)&v;
            vh[0] = __hmul2(vh[0], sch);
            vh[1] = __hmul2(vh[1], sch);
            vh[2] = __hmul2(vh[2], sch);
            vh[3] = __hmul2(vh[3], sch);
            *(uint4*)(smem + PV_VF + row * 144 + c8 * 16) = v;
        }
        __syncthreads();

#pragma unroll
        for (int ks = 0; ks < 8; ks++) {
            uint32_t ah[4];
            ldsm4t(ah, aP + ks * 4352);          // 16 s-rows * 272B
#pragma unroll
            for (int g = 0; g < 4; g++) {
                uint32_t bv[4];
                ldsm4t(bv, aV + ks * 2304 + g * 32);
                mma_f16(c[2 * g],     ah, bv[0], bv[1]);
                mma_f16(c[2 * g + 1], ah, bv[2], bv[3]);
            }
        }
    }

    const long rowA = (long)b * TT + t0 + wid * 16 + (lane >> 2);
    const int col0 = (lane & 3) * 2;
#pragma unroll
    for (int n = 0; n < 8; n++) {
        float* o = &out[rowA * HH + n * 8 + col0];
        atomicAdd(&o[0], c[n][0]);
        atomicAdd(&o[1], c[n][1]);
        atomicAdd(&o[8 * HH + 0], c[n][2]);
        atomicAdd(&o[8 * HH + 1], c[n][3]);
    }
}

// ---------------------------------------------------------------------------
extern "C" void kernel_launch(void* const* d_in, const int* in_sizes, int n_in,
                              void* d_out, int out_size)
{
    const float* x  = (const float*)d_in[0];
    const float* Wq = (const float*)d_in[1];
    const float* Wk = (const float*)d_in[2];
    const float* Wv = (const float*)d_in[3];
    float* out = (float*)d_out;

    cudaFuncSetAttribute(proj_kernel, cudaFuncAttributeMaxDynamicSharedMemorySize,
                         PJ_SMEM);
    cudaFuncSetAttribute(sgemm_kernel, cudaFuncAttributeMaxDynamicSharedMemorySize,
                         SG_SMEM);
    cudaFuncSetAttribute(pv_kernel, cudaFuncAttributeMaxDynamicSharedMemorySize,
                         PV_SMEM);

    cudaMemsetAsync(out, 0, (size_t)out_size * sizeof(float), 0);

    convw_kernel<<<dim3(256, 3, 1), 256>>>(Wq, Wk, Wv);
    proj_kernel<<<BB * TT / 128, 256, PJ_SMEM>>>(x);
    sgemm_kernel<<<dim3(NPAIR, BB, 1), 256, SG_SMEM>>>();
    merge_kernel<<<(BB * TT * 4 + 255) / 256, 256>>>();
    pv_kernel<<<dim3(PV_NPAIR, BB, 1), 256, PV_SMEM>>>(out);
}